// round 10
// baseline (speedup 1.0000x reference)
#include <cuda_runtime.h>
#include <cuda_bf16.h>
#include <cstdint>

// ---------------------------------------------------------------------------
// W8A8 dynamic-quant linear:  y = (q8(x) @ W^T) * act_scale * w_scale + bias
// TOK=4096, K=4096, OUT(N)=12288
//
// Round 10: round 9's NaN = barrier placed BEFORE cp.async wait_group
// (cross-thread visibility race) + impossible reg budget (4 warps/SMSP x 226
// regs > 16K/SMSP). Fix: round-7 shape (512 thr, 32x64 warp tiles, 126 regs,
// 4 warps/SMSP, proven addressing) + corrected single-barrier 3-stage
// pipeline: wait_group -> __syncthreads -> copy(c+2) -> compute(c).
// ---------------------------------------------------------------------------

#define TOK   4096
#define KDIM  4096
#define NDIM  12288

#define TILE_M 128
#define TILE_N 256
#define NCH    64                // 128-B (64-elem) bf16 K-chunks
#define KCB    128
#define NSTAGE 3

#define ROWB   144               // 128 B + 16 B pad
#define A_BYTES (TILE_M * ROWB)  // 18432
#define B_BYTES (TILE_N * ROWB)  // 36864
#define STAGE_BYTES (A_BYTES + B_BYTES)   // 55296

// SMEM layout (bytes)
#define SM_WS 0                  // 256 floats
#define SM_BS 1024               // 256 floats
#define SM_AB 2048
#define SMEM_TOTAL (SM_AB + NSTAGE * STAGE_BYTES)   // 167936

#define W_ELEMS ((size_t)NDIM * KDIM)

// Scratch (module globals -- allocation-free per harness rules)
__device__ __nv_bfloat16 g_xbf[(size_t)TOK * KDIM];
__device__ __nv_bfloat16 g_wbf[W_ELEMS];
__device__ float         g_ascale[TOK];
__device__ int           g_wmode;   // 0=int8 raw, 1=int32, 2=bf16, 3=f32

// ---------------------------------------------------------------------------
__device__ __forceinline__ uint32_t smem_u32(const void* p) {
    uint32_t a;
    asm("{ .reg .u64 t; cvta.to.shared.u64 t, %1; cvt.u32.u64 %0, t; }" : "=r"(a) : "l"(p));
    return a;
}

__device__ __forceinline__ void cp16(uint32_t dst, const void* src) {
    asm volatile("cp.async.cg.shared.global [%0], [%1], 16;" :: "r"(dst), "l"(src));
}

__device__ __forceinline__ void ldsm_x4(uint32_t* r, uint32_t addr) {
    asm volatile("ldmatrix.sync.aligned.m8n8.x4.shared.b16 {%0,%1,%2,%3}, [%4];"
                 : "=r"(r[0]), "=r"(r[1]), "=r"(r[2]), "=r"(r[3]) : "r"(addr));
}

__device__ __forceinline__ void mma_bf16_k16(float* c, const uint32_t* a, uint32_t b0, uint32_t b1) {
    asm volatile(
        "mma.sync.aligned.m16n8k16.row.col.f32.bf16.bf16.f32 "
        "{%0,%1,%2,%3}, {%4,%5,%6,%7}, {%8,%9}, {%0,%1,%2,%3};"
        : "+f"(c[0]), "+f"(c[1]), "+f"(c[2]), "+f"(c[3])
        : "r"(a[0]), "r"(a[1]), "r"(a[2]), "r"(a[3]), "r"(b0), "r"(b1));
}

// ---------------------------------------------------------------------------
// Weight format autodetect + direct-to-bf16 pack (proven rounds 4/7)
// ---------------------------------------------------------------------------
__global__ void detect_kernel(const void* w) {
    __shared__ int ok32, okf32, okbf;
    int tid = threadIdx.x;
    if (tid == 0) { ok32 = 1; okf32 = 1; okbf = 1; }
    __syncthreads();
    const int*            wi = (const int*)w;
    const float*          wf = (const float*)w;
    const __nv_bfloat16*  wb = (const __nv_bfloat16*)w;
#pragma unroll
    for (int i = 0; i < 4; i++) {
        int idx = tid * 4 + i;
        int v = wi[idx];
        if (v < -128 || v > 127) ok32 = 0;
        float f = wf[idx];
        if (!(f == rintf(f)) || f < -128.0f || f > 127.0f) okf32 = 0;
        float b = __bfloat162float(wb[idx]);
        if (!(b == rintf(b)) || b < -128.0f || b > 127.0f) okbf = 0;
    }
    __syncthreads();
    if (tid == 0)
        g_wmode = ok32 ? 1 : (okf32 ? 3 : (okbf ? 2 : 0));
}

__global__ void __launch_bounds__(256) pack_kernel(const void* w) {
    size_t g = (size_t)blockIdx.x * blockDim.x + threadIdx.x;
    if (g * 16 >= W_ELEMS) return;
    int mode = g_wmode;
    float f[16];
    if (mode == 0) {
        int8_t b[16];
        *(int4*)b = ((const int4*)w)[g];
#pragma unroll
        for (int j = 0; j < 16; j++) f[j] = (float)b[j];
    } else if (mode == 1) {
        const int4* wi = (const int4*)w + g * 4;
#pragma unroll
        for (int j = 0; j < 4; j++) {
            int4 v = wi[j];
            f[j * 4 + 0] = (float)(int8_t)v.x; f[j * 4 + 1] = (float)(int8_t)v.y;
            f[j * 4 + 2] = (float)(int8_t)v.z; f[j * 4 + 3] = (float)(int8_t)v.w;
        }
    } else if (mode == 2) {
        const __nv_bfloat16* wb = (const __nv_bfloat16*)w + g * 16;
#pragma unroll
        for (int j = 0; j < 16; j++) f[j] = __bfloat162float(wb[j]);
    } else {
        const float4* wf = (const float4*)w + g * 4;
#pragma unroll
        for (int j = 0; j < 4; j++) {
            float4 v = wf[j];
            f[j * 4 + 0] = v.x; f[j * 4 + 1] = v.y;
            f[j * 4 + 2] = v.z; f[j * 4 + 3] = v.w;
        }
    }
    uint32_t o[8];
#pragma unroll
    for (int j = 0; j < 8; j++) {
        __nv_bfloat162 h = __floats2bfloat162_rn(f[2 * j], f[2 * j + 1]);
        o[j] = *(uint32_t*)&h;
    }
    uint4* dst = (uint4*)(g_wbf + g * 16);
    dst[0] = make_uint4(o[0], o[1], o[2], o[3]);
    dst[1] = make_uint4(o[4], o[5], o[6], o[7]);
}

// ---------------------------------------------------------------------------
// Kernel 1: per-token dynamic quantization -> bf16 (int-valued)
// ---------------------------------------------------------------------------
__device__ __forceinline__ float q8f(float x, float s) {
    float r = rintf(__fdiv_rn(x, s));
    return fminf(fmaxf(r, -128.0f), 127.0f);
}

__global__ void __launch_bounds__(256) quant_kernel(const float* __restrict__ x) {
    int t = blockIdx.x;
    int tid = threadIdx.x;
    const float4* xr = (const float4*)(x + (size_t)t * KDIM);
    float4 v[4];
    float am = 0.0f;
#pragma unroll
    for (int i = 0; i < 4; i++) {
        v[i] = xr[tid * 4 + i];
        am = fmaxf(am, fmaxf(fmaxf(fabsf(v[i].x), fabsf(v[i].y)),
                             fmaxf(fabsf(v[i].z), fabsf(v[i].w))));
    }
    __shared__ float red[256];
    red[tid] = am;
    __syncthreads();
    for (int s = 128; s > 0; s >>= 1) {
        if (tid < s) red[tid] = fmaxf(red[tid], red[tid + s]);
        __syncthreads();
    }
    float s = fmaxf(__fdiv_rn(red[0], 127.0f), 1e-8f);
    if (tid == 0) g_ascale[t] = s;

    float q[16];
    q[0] = q8f(v[0].x, s);  q[1] = q8f(v[0].y, s);  q[2] = q8f(v[0].z, s);  q[3] = q8f(v[0].w, s);
    q[4] = q8f(v[1].x, s);  q[5] = q8f(v[1].y, s);  q[6] = q8f(v[1].z, s);  q[7] = q8f(v[1].w, s);
    q[8] = q8f(v[2].x, s);  q[9] = q8f(v[2].y, s);  q[10] = q8f(v[2].z, s); q[11] = q8f(v[2].w, s);
    q[12] = q8f(v[3].x, s); q[13] = q8f(v[3].y, s); q[14] = q8f(v[3].z, s); q[15] = q8f(v[3].w, s);

    uint32_t h[8];
#pragma unroll
    for (int j = 0; j < 8; j++) {
        __nv_bfloat162 hb = __floats2bfloat162_rn(q[2 * j], q[2 * j + 1]);
        h[j] = *(uint32_t*)&hb;
    }
    uint4* dst = (uint4*)(g_xbf + (size_t)t * KDIM + tid * 16);
    dst[0] = make_uint4(h[0], h[1], h[2], h[3]);
    dst[1] = make_uint4(h[4], h[5], h[6], h[7]);
}

// ---------------------------------------------------------------------------
// GEMM: bf16 HMMA, 128x256 tile, 512 thr (16 warps x 32x64), 3-stage 128B chunks
// ---------------------------------------------------------------------------
__device__ __forceinline__ void copy_chunk(const __nv_bfloat16* abase_g,
                                           const __nv_bfloat16* bbase_g,
                                           int c, int stage, uint32_t sb, int tid) {
    uint32_t st = sb + SM_AB + stage * STAGE_BYTES;
    // A: 128 rows x 128 B = 1024 cp16 -> 2 per thread
    const char* asrc = (const char*)abase_g + (size_t)c * KCB;
#pragma unroll
    for (int i = 0; i < 2; i++) {
        int idx = tid + i * 512;
        int row = idx >> 3, u = idx & 7;
        cp16(st + row * ROWB + u * 16, asrc + (size_t)row * (KDIM * 2) + u * 16);
    }
    // B: 256 rows x 128 B = 2048 cp16 -> 4 per thread
    const char* bsrc = (const char*)bbase_g + (size_t)c * KCB;
    uint32_t bb = st + A_BYTES;
#pragma unroll
    for (int i = 0; i < 4; i++) {
        int idx = tid + i * 512;
        int row = idx >> 3, u = idx & 7;
        cp16(bb + row * ROWB + u * 16, bsrc + (size_t)row * (KDIM * 2) + u * 16);
    }
}

__global__ void __launch_bounds__(512, 1) hmma_gemm(const float* __restrict__ wscale,
                                                    const float* __restrict__ bias,
                                                    float* __restrict__ out) {
    extern __shared__ char smem[];
    uint32_t sb = smem_u32(smem);
    int tid = threadIdx.x, wid = tid >> 5, lane = tid & 31;
    int m0 = blockIdx.y * TILE_M;
    int n0 = blockIdx.x * TILE_N;
    int wm = wid & 3;            // 4 M-strips of 32
    int wn = wid >> 2;           // 4 N-strips of 64

    float* smem_ws = (float*)(smem + SM_WS);
    float* smem_bs = (float*)(smem + SM_BS);
    if (tid < 256)      smem_ws[tid] = wscale[n0 + tid];
    else                smem_bs[tid - 256] = bias[n0 + tid - 256];

    int g = lane >> 3, lr = lane & 7;
    uint32_t aoff = (uint32_t)((wm * 32 + (g & 1) * 8 + lr) * ROWB + (g >> 1) * 16);
    uint32_t boff = (uint32_t)(A_BYTES + (wn * 64 + (g >> 1) * 8 + lr) * ROWB + (g & 1) * 16);

    float acc[2][8][4];
#pragma unroll
    for (int f = 0; f < 2; f++)
#pragma unroll
        for (int nf = 0; nf < 8; nf++)
#pragma unroll
            for (int i = 0; i < 4; i++) acc[f][nf][i] = 0.0f;

    const __nv_bfloat16* Ag = g_xbf + (size_t)m0 * KDIM;
    const __nv_bfloat16* Bg = g_wbf + (size_t)n0 * KDIM;

    copy_chunk(Ag, Bg, 0, 0, sb, tid);
    asm volatile("cp.async.commit_group;" ::: "memory");
    copy_chunk(Ag, Bg, 1, 1, sb, tid);
    asm volatile("cp.async.commit_group;" ::: "memory");

    for (int c = 0; c < NCH; c++) {
        // own-thread chunk c complete (allow chunk c+1 in flight)
        if (c < NCH - 1) asm volatile("cp.async.wait_group 1;" ::: "memory");
        else             asm volatile("cp.async.wait_group 0;" ::: "memory");
        // cross-thread visibility of chunk c + all warps done computing c-1
        __syncthreads();
        // overwrite stage (c+2)%3 == (c-1)%3 -- safe after barrier
        if (c + 2 < NCH) {
            copy_chunk(Ag, Bg, c + 2, (c + 2) % NSTAGE, sb, tid);
            asm volatile("cp.async.commit_group;" ::: "memory");
        }

        uint32_t st = sb + SM_AB + (c % NSTAGE) * STAGE_BYTES;
#pragma unroll
        for (int ks = 0; ks < 4; ks++) {      // 4 x k16 (32 B) per 128-B chunk
            uint32_t a[2][4];
#pragma unroll
            for (int f = 0; f < 2; f++)
                ldsm_x4(a[f], st + aoff + f * (16 * ROWB) + ks * 32);
            uint32_t b[4][4];
#pragma unroll
            for (int q = 0; q < 4; q++)
                ldsm_x4(b[q], st + boff + q * (16 * ROWB) + ks * 32);
#pragma unroll
            for (int f = 0; f < 2; f++)
#pragma unroll
                for (int q = 0; q < 4; q++) {
                    mma_bf16_k16(acc[f][2 * q],     a[f], b[q][0], b[q][1]);
                    mma_bf16_k16(acc[f][2 * q + 1], a[f], b[q][2], b[q][3]);
                }
        }
    }

    int lrow = lane >> 2, lcol2 = (lane & 3) * 2;
#pragma unroll
    for (int f = 0; f < 2; f++) {
        int mA = m0 + wm * 32 + f * 16 + lrow;
        float as0 = g_ascale[mA];
        float as1 = g_ascale[mA + 8];
#pragma unroll
        for (int nf = 0; nf < 8; nf++) {
            int col = wn * 64 + nf * 8 + lcol2;
            float ws0 = smem_ws[col], ws1 = smem_ws[col + 1];
            float bs0 = smem_bs[col], bs1 = smem_bs[col + 1];
            float2 v0, v1;
            v0.x = fmaf(acc[f][nf][0] * as0, ws0, bs0);
            v0.y = fmaf(acc[f][nf][1] * as0, ws1, bs1);
            v1.x = fmaf(acc[f][nf][2] * as1, ws0, bs0);
            v1.y = fmaf(acc[f][nf][3] * as1, ws1, bs1);
            *(float2*)(out + (size_t)mA * NDIM + n0 + col) = v0;
            *(float2*)(out + (size_t)(mA + 8) * NDIM + n0 + col) = v1;
        }
    }
}

// ---------------------------------------------------------------------------
extern "C" void kernel_launch(void* const* d_in, const int* in_sizes, int n_in,
                              void* d_out, int out_size) {
    const float* x;
    const float* bs;
    if (in_sizes[0] == NDIM) {           // alphabetical: bias first
        bs = (const float*)d_in[0];
        x  = (const float*)d_in[3];
    } else {                             // dict order: x first
        x  = (const float*)d_in[0];
        bs = (const float*)d_in[3];
    }
    const void*  w  = d_in[1];
    const float* ws = (const float*)d_in[2];
    float* out = (float*)d_out;

    cudaFuncSetAttribute(hmma_gemm, cudaFuncAttributeMaxDynamicSharedMemorySize, SMEM_TOTAL);

    detect_kernel<<<1, 256>>>(w);
    pack_kernel<<<(int)((W_ELEMS / 16 + 255) / 256), 256>>>(w);
    quant_kernel<<<TOK, 256>>>(x);
    dim3 grid(NDIM / TILE_N, TOK / TILE_M);   // (48, 32)
    hmma_gemm<<<grid, 512, SMEM_TOTAL>>>(ws, bs, out);
}

// round 11
// speedup vs baseline: 1.0494x; 1.0494x over previous
#include <cuda_runtime.h>
#include <cuda_bf16.h>
#include <cstdint>

// ---------------------------------------------------------------------------
// W8A8 dynamic-quant linear:  y = (q8(x) @ W^T) * act_scale * w_scale + bias
// TOK=4096, K=4096, OUT(N)=12288
//
// Round 11: round-8 config (best: 256 thr, 64x64 warp tiles, 2-stage 256-B
// chunks, tensor 57%) + software-pipelined fragments: B[q+1] prefetched under
// MMAs of q, A(ks+1) prefetched at q==1, A ping-pong by ks parity (template
// steps keep arrays in registers). Converts ldsm->mma dependency stalls into
// overlap. ~210 regs, no spills expected.
// ---------------------------------------------------------------------------

#define TOK   4096
#define KDIM  4096
#define NDIM  12288

#define TILE_M 128
#define TILE_N 256
#define NCH    32                // 256-B (128-elem) bf16 K-chunks
#define KCB    256

#define ROWB   272               // 256 B + 16 B pad
#define A_BYTES (TILE_M * ROWB)  // 34816
#define B_BYTES (TILE_N * ROWB)  // 69632
#define STAGE_BYTES (A_BYTES + B_BYTES)   // 104448

// SMEM layout (bytes)
#define SM_WS 0
#define SM_BS 1024
#define SM_AB 2048
#define SMEM_TOTAL (SM_AB + 2 * STAGE_BYTES)   // 210944

#define W_ELEMS ((size_t)NDIM * KDIM)

// Scratch (module globals -- allocation-free per harness rules)
__device__ __nv_bfloat16 g_xbf[(size_t)TOK * KDIM];
__device__ __nv_bfloat16 g_wbf[W_ELEMS];
__device__ float         g_ascale[TOK];
__device__ int           g_wmode;   // 0=int8 raw, 1=int32, 2=bf16, 3=f32

// ---------------------------------------------------------------------------
__device__ __forceinline__ uint32_t smem_u32(const void* p) {
    uint32_t a;
    asm("{ .reg .u64 t; cvta.to.shared.u64 t, %1; cvt.u32.u64 %0, t; }" : "=r"(a) : "l"(p));
    return a;
}

__device__ __forceinline__ void cp16(uint32_t dst, const void* src) {
    asm volatile("cp.async.cg.shared.global [%0], [%1], 16;" :: "r"(dst), "l"(src));
}

__device__ __forceinline__ void ldsm_x4(uint32_t* r, uint32_t addr) {
    asm volatile("ldmatrix.sync.aligned.m8n8.x4.shared.b16 {%0,%1,%2,%3}, [%4];"
                 : "=r"(r[0]), "=r"(r[1]), "=r"(r[2]), "=r"(r[3]) : "r"(addr));
}

__device__ __forceinline__ void mma_bf16_k16(float* c, const uint32_t* a, uint32_t b0, uint32_t b1) {
    asm volatile(
        "mma.sync.aligned.m16n8k16.row.col.f32.bf16.bf16.f32 "
        "{%0,%1,%2,%3}, {%4,%5,%6,%7}, {%8,%9}, {%0,%1,%2,%3};"
        : "+f"(c[0]), "+f"(c[1]), "+f"(c[2]), "+f"(c[3])
        : "r"(a[0]), "r"(a[1]), "r"(a[2]), "r"(a[3]), "r"(b0), "r"(b1));
}

// ---------------------------------------------------------------------------
// Weight format autodetect + direct-to-bf16 pack (proven rounds 4/7)
// ---------------------------------------------------------------------------
__global__ void detect_kernel(const void* w) {
    __shared__ int ok32, okf32, okbf;
    int tid = threadIdx.x;
    if (tid == 0) { ok32 = 1; okf32 = 1; okbf = 1; }
    __syncthreads();
    const int*            wi = (const int*)w;
    const float*          wf = (const float*)w;
    const __nv_bfloat16*  wb = (const __nv_bfloat16*)w;
#pragma unroll
    for (int i = 0; i < 4; i++) {
        int idx = tid * 4 + i;
        int v = wi[idx];
        if (v < -128 || v > 127) ok32 = 0;
        float f = wf[idx];
        if (!(f == rintf(f)) || f < -128.0f || f > 127.0f) okf32 = 0;
        float b = __bfloat162float(wb[idx]);
        if (!(b == rintf(b)) || b < -128.0f || b > 127.0f) okbf = 0;
    }
    __syncthreads();
    if (tid == 0)
        g_wmode = ok32 ? 1 : (okf32 ? 3 : (okbf ? 2 : 0));
}

__global__ void __launch_bounds__(256) pack_kernel(const void* w) {
    size_t g = (size_t)blockIdx.x * blockDim.x + threadIdx.x;
    if (g * 16 >= W_ELEMS) return;
    int mode = g_wmode;
    float f[16];
    if (mode == 0) {
        int8_t b[16];
        *(int4*)b = ((const int4*)w)[g];
#pragma unroll
        for (int j = 0; j < 16; j++) f[j] = (float)b[j];
    } else if (mode == 1) {
        const int4* wi = (const int4*)w + g * 4;
#pragma unroll
        for (int j = 0; j < 4; j++) {
            int4 v = wi[j];
            f[j * 4 + 0] = (float)(int8_t)v.x; f[j * 4 + 1] = (float)(int8_t)v.y;
            f[j * 4 + 2] = (float)(int8_t)v.z; f[j * 4 + 3] = (float)(int8_t)v.w;
        }
    } else if (mode == 2) {
        const __nv_bfloat16* wb = (const __nv_bfloat16*)w + g * 16;
#pragma unroll
        for (int j = 0; j < 16; j++) f[j] = __bfloat162float(wb[j]);
    } else {
        const float4* wf = (const float4*)w + g * 4;
#pragma unroll
        for (int j = 0; j < 4; j++) {
            float4 v = wf[j];
            f[j * 4 + 0] = v.x; f[j * 4 + 1] = v.y;
            f[j * 4 + 2] = v.z; f[j * 4 + 3] = v.w;
        }
    }
    uint32_t o[8];
#pragma unroll
    for (int j = 0; j < 8; j++) {
        __nv_bfloat162 h = __floats2bfloat162_rn(f[2 * j], f[2 * j + 1]);
        o[j] = *(uint32_t*)&h;
    }
    uint4* dst = (uint4*)(g_wbf + g * 16);
    dst[0] = make_uint4(o[0], o[1], o[2], o[3]);
    dst[1] = make_uint4(o[4], o[5], o[6], o[7]);
}

// ---------------------------------------------------------------------------
// Kernel 1: per-token dynamic quantization -> bf16 (int-valued)
// ---------------------------------------------------------------------------
__device__ __forceinline__ float q8f(float x, float s) {
    float r = rintf(__fdiv_rn(x, s));
    return fminf(fmaxf(r, -128.0f), 127.0f);
}

__global__ void __launch_bounds__(256) quant_kernel(const float* __restrict__ x) {
    int t = blockIdx.x;
    int tid = threadIdx.x;
    const float4* xr = (const float4*)(x + (size_t)t * KDIM);
    float4 v[4];
    float am = 0.0f;
#pragma unroll
    for (int i = 0; i < 4; i++) {
        v[i] = xr[tid * 4 + i];
        am = fmaxf(am, fmaxf(fmaxf(fabsf(v[i].x), fabsf(v[i].y)),
                             fmaxf(fabsf(v[i].z), fabsf(v[i].w))));
    }
    __shared__ float red[256];
    red[tid] = am;
    __syncthreads();
    for (int s = 128; s > 0; s >>= 1) {
        if (tid < s) red[tid] = fmaxf(red[tid], red[tid + s]);
        __syncthreads();
    }
    float s = fmaxf(__fdiv_rn(red[0], 127.0f), 1e-8f);
    if (tid == 0) g_ascale[t] = s;

    float q[16];
    q[0] = q8f(v[0].x, s);  q[1] = q8f(v[0].y, s);  q[2] = q8f(v[0].z, s);  q[3] = q8f(v[0].w, s);
    q[4] = q8f(v[1].x, s);  q[5] = q8f(v[1].y, s);  q[6] = q8f(v[1].z, s);  q[7] = q8f(v[1].w, s);
    q[8] = q8f(v[2].x, s);  q[9] = q8f(v[2].y, s);  q[10] = q8f(v[2].z, s); q[11] = q8f(v[2].w, s);
    q[12] = q8f(v[3].x, s); q[13] = q8f(v[3].y, s); q[14] = q8f(v[3].z, s); q[15] = q8f(v[3].w, s);

    uint32_t h[8];
#pragma unroll
    for (int j = 0; j < 8; j++) {
        __nv_bfloat162 hb = __floats2bfloat162_rn(q[2 * j], q[2 * j + 1]);
        h[j] = *(uint32_t*)&hb;
    }
    uint4* dst = (uint4*)(g_xbf + (size_t)t * KDIM + tid * 16);
    dst[0] = make_uint4(h[0], h[1], h[2], h[3]);
    dst[1] = make_uint4(h[4], h[5], h[6], h[7]);
}

// ---------------------------------------------------------------------------
// GEMM: bf16 HMMA, 128x256 tile, 256 thr (8 warps x 64x64), 2-stage 256B
// chunks, software-pipelined fragments
// ---------------------------------------------------------------------------
__device__ __forceinline__ void copy_chunk(const __nv_bfloat16* abase_g,
                                           const __nv_bfloat16* bbase_g,
                                           int c, int stage, uint32_t sb, int tid) {
    uint32_t st = sb + SM_AB + stage * STAGE_BYTES;
    // A: 128 rows x 256 B = 2048 cp16 -> 8 per thread
    const char* asrc = (const char*)abase_g + (size_t)c * KCB;
#pragma unroll
    for (int i = 0; i < 8; i++) {
        int idx = tid + i * 256;
        int row = idx >> 4, u = idx & 15;
        cp16(st + row * ROWB + u * 16, asrc + (size_t)row * (KDIM * 2) + u * 16);
    }
    // B: 256 rows x 256 B = 4096 cp16 -> 16 per thread
    const char* bsrc = (const char*)bbase_g + (size_t)c * KCB;
    uint32_t bb = st + A_BYTES;
#pragma unroll
    for (int i = 0; i < 16; i++) {
        int idx = tid + i * 256;
        int row = idx >> 4, u = idx & 15;
        cp16(bb + row * ROWB + u * 16, bsrc + (size_t)row * (KDIM * 2) + u * 16);
    }
}

// One k16-step with fragment prefetch. Ac = current A frags (this ks),
// An = next A frags (filled for ks+1). Bc holds B[q=0] on entry; body
// prefetches B[q+1] (or B[0] of ks+1) under the MMAs of q.
template<int KS>
__device__ __forceinline__ void ks_step(uint32_t st, uint32_t aoff, uint32_t boff,
                                        uint32_t (&Ac)[4][4], uint32_t (&An)[4][4],
                                        uint32_t (&Bc)[4], float (&acc)[4][8][4]) {
#pragma unroll
    for (int q = 0; q < 4; q++) {
        uint32_t Bn[4];
        if (q < 3)        ldsm_x4(Bn, st + boff + (q + 1) * (16 * ROWB) + KS * 32);
        else if (KS < 7)  ldsm_x4(Bn, st + boff + (KS + 1) * 32);
        if (q == 1 && KS < 7) {
#pragma unroll
            for (int f = 0; f < 4; f++)
                ldsm_x4(An[f], st + aoff + f * (16 * ROWB) + (KS + 1) * 32);
        }
#pragma unroll
        for (int f = 0; f < 4; f++) {
            mma_bf16_k16(acc[f][2 * q],     Ac[f], Bc[0], Bc[1]);
            mma_bf16_k16(acc[f][2 * q + 1], Ac[f], Bc[2], Bc[3]);
        }
        if (q < 3 || KS < 7) {
#pragma unroll
            for (int i = 0; i < 4; i++) Bc[i] = Bn[i];
        }
    }
}

__global__ void __launch_bounds__(256, 1) hmma_gemm(const float* __restrict__ wscale,
                                                    const float* __restrict__ bias,
                                                    float* __restrict__ out) {
    extern __shared__ char smem[];
    uint32_t sb = smem_u32(smem);
    int tid = threadIdx.x, wid = tid >> 5, lane = tid & 31;
    int m0 = blockIdx.y * TILE_M;
    int n0 = blockIdx.x * TILE_N;
    int wm = wid & 1;            // 2 M-strips of 64
    int wn = wid >> 1;           // 4 N-strips of 64

    float* smem_ws = (float*)(smem + SM_WS);
    float* smem_bs = (float*)(smem + SM_BS);
    smem_ws[tid] = wscale[n0 + tid];
    smem_bs[tid] = bias[n0 + tid];

    int g = lane >> 3, lr = lane & 7;
    uint32_t aoff = (uint32_t)((wm * 64 + (g & 1) * 8 + lr) * ROWB + (g >> 1) * 16);
    uint32_t boff = (uint32_t)(A_BYTES + (wn * 64 + (g >> 1) * 8 + lr) * ROWB + (g & 1) * 16);

    float acc[4][8][4];
#pragma unroll
    for (int f = 0; f < 4; f++)
#pragma unroll
        for (int nf = 0; nf < 8; nf++)
#pragma unroll
            for (int i = 0; i < 4; i++) acc[f][nf][i] = 0.0f;

    const __nv_bfloat16* Ag = g_xbf + (size_t)m0 * KDIM;
    const __nv_bfloat16* Bg = g_wbf + (size_t)n0 * KDIM;

    copy_chunk(Ag, Bg, 0, 0, sb, tid);
    asm volatile("cp.async.commit_group;" ::: "memory");

    uint32_t A0[4][4], A1[4][4], Bc[4];

    for (int c = 0; c < NCH; c++) {
        asm volatile("cp.async.wait_group 0;" ::: "memory");   // own chunk c done
        __syncthreads();          // cross-thread visibility + all warps off c-1
        if (c + 1 < NCH) {
            copy_chunk(Ag, Bg, c + 1, (c + 1) & 1, sb, tid);
            asm volatile("cp.async.commit_group;" ::: "memory");
        }
        uint32_t st = sb + SM_AB + (c & 1) * STAGE_BYTES;

        // preload ks=0 fragments
#pragma unroll
        for (int f = 0; f < 4; f++)
            ldsm_x4(A0[f], st + aoff + f * (16 * ROWB));
        ldsm_x4(Bc, st + boff);

        ks_step<0>(st, aoff, boff, A0, A1, Bc, acc);
        ks_step<1>(st, aoff, boff, A1, A0, Bc, acc);
        ks_step<2>(st, aoff, boff, A0, A1, Bc, acc);
        ks_step<3>(st, aoff, boff, A1, A0, Bc, acc);
        ks_step<4>(st, aoff, boff, A0, A1, Bc, acc);
        ks_step<5>(st, aoff, boff, A1, A0, Bc, acc);
        ks_step<6>(st, aoff, boff, A0, A1, Bc, acc);
        ks_step<7>(st, aoff, boff, A1, A0, Bc, acc);
    }

    int lrow = lane >> 2, lcol2 = (lane & 3) * 2;
#pragma unroll
    for (int f = 0; f < 4; f++) {
        int mA = m0 + wm * 64 + f * 16 + lrow;
        float as0 = g_ascale[mA];
        float as1 = g_ascale[mA + 8];
#pragma unroll
        for (int nf = 0; nf < 8; nf++) {
            int col = wn * 64 + nf * 8 + lcol2;
            float ws0 = smem_ws[col], ws1 = smem_ws[col + 1];
            float bs0 = smem_bs[col], bs1 = smem_bs[col + 1];
            float2 v0, v1;
            v0.x = fmaf(acc[f][nf][0] * as0, ws0, bs0);
            v0.y = fmaf(acc[f][nf][1] * as0, ws1, bs1);
            v1.x = fmaf(acc[f][nf][2] * as1, ws0, bs0);
            v1.y = fmaf(acc[f][nf][3] * as1, ws1, bs1);
            *(float2*)(out + (size_t)mA * NDIM + n0 + col) = v0;
            *(float2*)(out + (size_t)(mA + 8) * NDIM + n0 + col) = v1;
        }
    }
}

// ---------------------------------------------------------------------------
extern "C" void kernel_launch(void* const* d_in, const int* in_sizes, int n_in,
                              void* d_out, int out_size) {
    const float* x;
    const float* bs;
    if (in_sizes[0] == NDIM) {           // alphabetical: bias first
        bs = (const float*)d_in[0];
        x  = (const float*)d_in[3];
    } else {                             // dict order: x first
        x  = (const float*)d_in[0];
        bs = (const float*)d_in[3];
    }
    const void*  w  = d_in[1];
    const float* ws = (const float*)d_in[2];
    float* out = (float*)d_out;

    cudaFuncSetAttribute(hmma_gemm, cudaFuncAttributeMaxDynamicSharedMemorySize, SMEM_TOTAL);

    detect_kernel<<<1, 256>>>(w);
    pack_kernel<<<(int)((W_ELEMS / 16 + 255) / 256), 256>>>(w);
    quant_kernel<<<TOK, 256>>>(x);
    dim3 grid(NDIM / TILE_N, TOK / TILE_M);   // (48, 32)
    hmma_gemm<<<grid, 256, SMEM_TOTAL>>>(ws, bs, out);
}

// round 12
// speedup vs baseline: 1.1542x; 1.0999x over previous
#include <cuda_runtime.h>
#include <cuda_bf16.h>
#include <cstdint>

// ---------------------------------------------------------------------------
// W8A8 dynamic-quant linear:  y = (q8(x) @ W^T) * act_scale * w_scale + bias
// TOK=4096, K=4096, OUT(N)=12288
//
// Round 12: tensor% is pinned at 52-57% across ALL intra-CTA structure
// changes -> per-chunk serial phases (wait/barrier/copy) with 1 CTA/SM are
// the bottleneck. Run 2 CTAs/SM: tile 128x128, 256 thr, 8 warps of 32x64
// (126 regs -> 4 warps/SMSP fits RF), smem 112.6 KB/CTA -> 2 CTAs resident.
// Proven R10 pipeline order (wait_group -> syncthreads -> copy -> compute).
// ---------------------------------------------------------------------------

#define TOK   4096
#define KDIM  4096
#define NDIM  12288

#define TILE_M 128
#define TILE_N 128
#define NCH    64                // 128-B (64-elem) bf16 K-chunks
#define KCB    128
#define NSTAGE 3

#define ROWB   144               // 128 B + 16 B pad
#define A_BYTES (TILE_M * ROWB)  // 18432
#define B_BYTES (TILE_N * ROWB)  // 18432
#define STAGE_BYTES (A_BYTES + B_BYTES)   // 36864

// SMEM layout (bytes)
#define SM_WS 0                  // 128 floats
#define SM_BS 512                // 128 floats
#define SM_AB 2048
#define SMEM_TOTAL (SM_AB + NSTAGE * STAGE_BYTES)   // 112640  (2 CTAs/SM)

#define W_ELEMS ((size_t)NDIM * KDIM)

// Scratch (module globals -- allocation-free per harness rules)
__device__ __nv_bfloat16 g_xbf[(size_t)TOK * KDIM];
__device__ __nv_bfloat16 g_wbf[W_ELEMS];
__device__ float         g_ascale[TOK];
__device__ int           g_wmode;   // 0=int8 raw, 1=int32, 2=bf16, 3=f32

// ---------------------------------------------------------------------------
__device__ __forceinline__ uint32_t smem_u32(const void* p) {
    uint32_t a;
    asm("{ .reg .u64 t; cvta.to.shared.u64 t, %1; cvt.u32.u64 %0, t; }" : "=r"(a) : "l"(p));
    return a;
}

__device__ __forceinline__ void cp16(uint32_t dst, const void* src) {
    asm volatile("cp.async.cg.shared.global [%0], [%1], 16;" :: "r"(dst), "l"(src));
}

__device__ __forceinline__ void ldsm_x4(uint32_t* r, uint32_t addr) {
    asm volatile("ldmatrix.sync.aligned.m8n8.x4.shared.b16 {%0,%1,%2,%3}, [%4];"
                 : "=r"(r[0]), "=r"(r[1]), "=r"(r[2]), "=r"(r[3]) : "r"(addr));
}

__device__ __forceinline__ void mma_bf16_k16(float* c, const uint32_t* a, uint32_t b0, uint32_t b1) {
    asm volatile(
        "mma.sync.aligned.m16n8k16.row.col.f32.bf16.bf16.f32 "
        "{%0,%1,%2,%3}, {%4,%5,%6,%7}, {%8,%9}, {%0,%1,%2,%3};"
        : "+f"(c[0]), "+f"(c[1]), "+f"(c[2]), "+f"(c[3])
        : "r"(a[0]), "r"(a[1]), "r"(a[2]), "r"(a[3]), "r"(b0), "r"(b1));
}

// ---------------------------------------------------------------------------
// Weight format autodetect + direct-to-bf16 pack (proven rounds 4/7)
// ---------------------------------------------------------------------------
__global__ void detect_kernel(const void* w) {
    __shared__ int ok32, okf32, okbf;
    int tid = threadIdx.x;
    if (tid == 0) { ok32 = 1; okf32 = 1; okbf = 1; }
    __syncthreads();
    const int*            wi = (const int*)w;
    const float*          wf = (const float*)w;
    const __nv_bfloat16*  wb = (const __nv_bfloat16*)w;
#pragma unroll
    for (int i = 0; i < 4; i++) {
        int idx = tid * 4 + i;
        int v = wi[idx];
        if (v < -128 || v > 127) ok32 = 0;
        float f = wf[idx];
        if (!(f == rintf(f)) || f < -128.0f || f > 127.0f) okf32 = 0;
        float b = __bfloat162float(wb[idx]);
        if (!(b == rintf(b)) || b < -128.0f || b > 127.0f) okbf = 0;
    }
    __syncthreads();
    if (tid == 0)
        g_wmode = ok32 ? 1 : (okf32 ? 3 : (okbf ? 2 : 0));
}

__global__ void __launch_bounds__(256) pack_kernel(const void* w) {
    size_t g = (size_t)blockIdx.x * blockDim.x + threadIdx.x;
    if (g * 16 >= W_ELEMS) return;
    int mode = g_wmode;
    float f[16];
    if (mode == 0) {
        int8_t b[16];
        *(int4*)b = ((const int4*)w)[g];
#pragma unroll
        for (int j = 0; j < 16; j++) f[j] = (float)b[j];
    } else if (mode == 1) {
        const int4* wi = (const int4*)w + g * 4;
#pragma unroll
        for (int j = 0; j < 4; j++) {
            int4 v = wi[j];
            f[j * 4 + 0] = (float)(int8_t)v.x; f[j * 4 + 1] = (float)(int8_t)v.y;
            f[j * 4 + 2] = (float)(int8_t)v.z; f[j * 4 + 3] = (float)(int8_t)v.w;
        }
    } else if (mode == 2) {
        const __nv_bfloat16* wb = (const __nv_bfloat16*)w + g * 16;
#pragma unroll
        for (int j = 0; j < 16; j++) f[j] = __bfloat162float(wb[j]);
    } else {
        const float4* wf = (const float4*)w + g * 4;
#pragma unroll
        for (int j = 0; j < 4; j++) {
            float4 v = wf[j];
            f[j * 4 + 0] = v.x; f[j * 4 + 1] = v.y;
            f[j * 4 + 2] = v.z; f[j * 4 + 3] = v.w;
        }
    }
    uint32_t o[8];
#pragma unroll
    for (int j = 0; j < 8; j++) {
        __nv_bfloat162 h = __floats2bfloat162_rn(f[2 * j], f[2 * j + 1]);
        o[j] = *(uint32_t*)&h;
    }
    uint4* dst = (uint4*)(g_wbf + g * 16);
    dst[0] = make_uint4(o[0], o[1], o[2], o[3]);
    dst[1] = make_uint4(o[4], o[5], o[6], o[7]);
}

// ---------------------------------------------------------------------------
// Kernel 1: per-token dynamic quantization -> bf16 (int-valued)
// ---------------------------------------------------------------------------
__device__ __forceinline__ float q8f(float x, float s) {
    float r = rintf(__fdiv_rn(x, s));
    return fminf(fmaxf(r, -128.0f), 127.0f);
}

__global__ void __launch_bounds__(256) quant_kernel(const float* __restrict__ x) {
    int t = blockIdx.x;
    int tid = threadIdx.x;
    const float4* xr = (const float4*)(x + (size_t)t * KDIM);
    float4 v[4];
    float am = 0.0f;
#pragma unroll
    for (int i = 0; i < 4; i++) {
        v[i] = xr[tid * 4 + i];
        am = fmaxf(am, fmaxf(fmaxf(fabsf(v[i].x), fabsf(v[i].y)),
                             fmaxf(fabsf(v[i].z), fabsf(v[i].w))));
    }
    __shared__ float red[256];
    red[tid] = am;
    __syncthreads();
    for (int s = 128; s > 0; s >>= 1) {
        if (tid < s) red[tid] = fmaxf(red[tid], red[tid + s]);
        __syncthreads();
    }
    float s = fmaxf(__fdiv_rn(red[0], 127.0f), 1e-8f);
    if (tid == 0) g_ascale[t] = s;

    float q[16];
    q[0] = q8f(v[0].x, s);  q[1] = q8f(v[0].y, s);  q[2] = q8f(v[0].z, s);  q[3] = q8f(v[0].w, s);
    q[4] = q8f(v[1].x, s);  q[5] = q8f(v[1].y, s);  q[6] = q8f(v[1].z, s);  q[7] = q8f(v[1].w, s);
    q[8] = q8f(v[2].x, s);  q[9] = q8f(v[2].y, s);  q[10] = q8f(v[2].z, s); q[11] = q8f(v[2].w, s);
    q[12] = q8f(v[3].x, s); q[13] = q8f(v[3].y, s); q[14] = q8f(v[3].z, s); q[15] = q8f(v[3].w, s);

    uint32_t h[8];
#pragma unroll
    for (int j = 0; j < 8; j++) {
        __nv_bfloat162 hb = __floats2bfloat162_rn(q[2 * j], q[2 * j + 1]);
        h[j] = *(uint32_t*)&hb;
    }
    uint4* dst = (uint4*)(g_xbf + (size_t)t * KDIM + tid * 16);
    dst[0] = make_uint4(h[0], h[1], h[2], h[3]);
    dst[1] = make_uint4(h[4], h[5], h[6], h[7]);
}

// ---------------------------------------------------------------------------
// GEMM: bf16 HMMA, 128x128 tile, 256 thr (8 warps x 32x64), 3-stage 128B
// chunks, 2 CTAs/SM
// ---------------------------------------------------------------------------
__device__ __forceinline__ void copy_chunk(const __nv_bfloat16* abase_g,
                                           const __nv_bfloat16* bbase_g,
                                           int c, int stage, uint32_t sb, int tid) {
    uint32_t st = sb + SM_AB + stage * STAGE_BYTES;
    // A: 128 rows x 128 B = 1024 cp16 -> 4 per thread
    const char* asrc = (const char*)abase_g + (size_t)c * KCB;
#pragma unroll
    for (int i = 0; i < 4; i++) {
        int idx = tid + i * 256;
        int row = idx >> 3, u = idx & 7;
        cp16(st + row * ROWB + u * 16, asrc + (size_t)row * (KDIM * 2) + u * 16);
    }
    // B: 128 rows x 128 B = 1024 cp16 -> 4 per thread
    const char* bsrc = (const char*)bbase_g + (size_t)c * KCB;
    uint32_t bb = st + A_BYTES;
#pragma unroll
    for (int i = 0; i < 4; i++) {
        int idx = tid + i * 256;
        int row = idx >> 3, u = idx & 7;
        cp16(bb + row * ROWB + u * 16, bsrc + (size_t)row * (KDIM * 2) + u * 16);
    }
}

__global__ void __launch_bounds__(256, 2) hmma_gemm(const float* __restrict__ wscale,
                                                    const float* __restrict__ bias,
                                                    float* __restrict__ out) {
    extern __shared__ char smem[];
    uint32_t sb = smem_u32(smem);
    int tid = threadIdx.x, wid = tid >> 5, lane = tid & 31;
    int m0 = blockIdx.y * TILE_M;
    int n0 = blockIdx.x * TILE_N;
    int wm = wid & 3;            // 4 M-strips of 32
    int wn = wid >> 2;           // 2 N-strips of 64

    float* smem_ws = (float*)(smem + SM_WS);
    float* smem_bs = (float*)(smem + SM_BS);
    if (tid < 128)      smem_ws[tid] = wscale[n0 + tid];
    else                smem_bs[tid - 128] = bias[n0 + tid - 128];

    int g = lane >> 3, lr = lane & 7;
    uint32_t aoff = (uint32_t)((wm * 32 + (g & 1) * 8 + lr) * ROWB + (g >> 1) * 16);
    uint32_t boff = (uint32_t)(A_BYTES + (wn * 64 + (g >> 1) * 8 + lr) * ROWB + (g & 1) * 16);

    float acc[2][8][4];
#pragma unroll
    for (int f = 0; f < 2; f++)
#pragma unroll
        for (int nf = 0; nf < 8; nf++)
#pragma unroll
            for (int i = 0; i < 4; i++) acc[f][nf][i] = 0.0f;

    const __nv_bfloat16* Ag = g_xbf + (size_t)m0 * KDIM;
    const __nv_bfloat16* Bg = g_wbf + (size_t)n0 * KDIM;

    copy_chunk(Ag, Bg, 0, 0, sb, tid);
    asm volatile("cp.async.commit_group;" ::: "memory");
    copy_chunk(Ag, Bg, 1, 1, sb, tid);
    asm volatile("cp.async.commit_group;" ::: "memory");

    for (int c = 0; c < NCH; c++) {
        // own-thread chunk c complete (chunk c+1 may remain in flight)
        if (c < NCH - 1) asm volatile("cp.async.wait_group 1;" ::: "memory");
        else             asm volatile("cp.async.wait_group 0;" ::: "memory");
        // cross-thread visibility of chunk c + all warps done with c-1
        __syncthreads();
        // stage (c+2)%3 == (c-1)%3 is free after the barrier
        if (c + 2 < NCH) {
            copy_chunk(Ag, Bg, c + 2, (c + 2) % NSTAGE, sb, tid);
            asm volatile("cp.async.commit_group;" ::: "memory");
        }

        uint32_t st = sb + SM_AB + (c % NSTAGE) * STAGE_BYTES;
#pragma unroll
        for (int ks = 0; ks < 4; ks++) {      // 4 x k16 (32 B) per 128-B chunk
            uint32_t a[2][4];
#pragma unroll
            for (int f = 0; f < 2; f++)
                ldsm_x4(a[f], st + aoff + f * (16 * ROWB) + ks * 32);
            uint32_t b[4][4];
#pragma unroll
            for (int q = 0; q < 4; q++)
                ldsm_x4(b[q], st + boff + q * (16 * ROWB) + ks * 32);
#pragma unroll
            for (int f = 0; f < 2; f++)
#pragma unroll
                for (int q = 0; q < 4; q++) {
                    mma_bf16_k16(acc[f][2 * q],     a[f], b[q][0], b[q][1]);
                    mma_bf16_k16(acc[f][2 * q + 1], a[f], b[q][2], b[q][3]);
                }
        }
    }

    int lrow = lane >> 2, lcol2 = (lane & 3) * 2;
#pragma unroll
    for (int f = 0; f < 2; f++) {
        int mA = m0 + wm * 32 + f * 16 + lrow;
        float as0 = g_ascale[mA];
        float as1 = g_ascale[mA + 8];
#pragma unroll
        for (int nf = 0; nf < 8; nf++) {
            int col = wn * 64 + nf * 8 + lcol2;
            float ws0 = smem_ws[col], ws1 = smem_ws[col + 1];
            float bs0 = smem_bs[col], bs1 = smem_bs[col + 1];
            float2 v0, v1;
            v0.x = fmaf(acc[f][nf][0] * as0, ws0, bs0);
            v0.y = fmaf(acc[f][nf][1] * as0, ws1, bs1);
            v1.x = fmaf(acc[f][nf][2] * as1, ws0, bs0);
            v1.y = fmaf(acc[f][nf][3] * as1, ws1, bs1);
            *(float2*)(out + (size_t)mA * NDIM + n0 + col) = v0;
            *(float2*)(out + (size_t)(mA + 8) * NDIM + n0 + col) = v1;
        }
    }
}

// ---------------------------------------------------------------------------
extern "C" void kernel_launch(void* const* d_in, const int* in_sizes, int n_in,
                              void* d_out, int out_size) {
    const float* x;
    const float* bs;
    if (in_sizes[0] == NDIM) {           // alphabetical: bias first
        bs = (const float*)d_in[0];
        x  = (const float*)d_in[3];
    } else {                             // dict order: x first
        x  = (const float*)d_in[0];
        bs = (const float*)d_in[3];
    }
    const void*  w  = d_in[1];
    const float* ws = (const float*)d_in[2];
    float* out = (float*)d_out;

    cudaFuncSetAttribute(hmma_gemm, cudaFuncAttributeMaxDynamicSharedMemorySize, SMEM_TOTAL);

    detect_kernel<<<1, 256>>>(w);
    pack_kernel<<<(int)((W_ELEMS / 16 + 255) / 256), 256>>>(w);
    quant_kernel<<<TOK, 256>>>(x);
    dim3 grid(NDIM / TILE_N, TOK / TILE_M);   // (96, 32)
    hmma_gemm<<<grid, 256, SMEM_TOTAL>>>(ws, bs, out);
}

// round 13
// speedup vs baseline: 1.3567x; 1.1754x over previous
#include <cuda_runtime.h>
#include <cuda_bf16.h>
#include <cstdint>

// ---------------------------------------------------------------------------
// W8A8 dynamic-quant linear:  y = (q8(x) @ W^T) * act_scale * w_scale + bias
// TOK=4096, K=4096, OUT(N)=12288
//
// Round 13: pad-144 layout had a 2-way ldmatrix bank conflict every phase
// (row stride 9 units -> window 31 wraps onto 0-2). Replace with XOR swizzle:
// ROWB=128, unit u of row r stored at u^(r&7). ldmatrix phases read 8
// consecutive rows at fixed u -> physical units u^0..u^7 all distinct ->
// conflict-free. Everything else = round-12 winner (2 CTAs/SM, 128x128 tile,
// 3-stage, wait->sync->copy->compute).
// ---------------------------------------------------------------------------

#define TOK   4096
#define KDIM  4096
#define NDIM  12288

#define TILE_M 128
#define TILE_N 128
#define NCH    64                // 128-B (64-elem) bf16 K-chunks
#define KCB    128
#define NSTAGE 3

#define ROWB   128               // no pad; XOR swizzle instead
#define A_BYTES (TILE_M * ROWB)  // 16384
#define B_BYTES (TILE_N * ROWB)  // 16384
#define STAGE_BYTES (A_BYTES + B_BYTES)   // 32768

// SMEM layout (bytes)
#define SM_WS 0                  // 128 floats
#define SM_BS 512                // 128 floats
#define SM_AB 2048
#define SMEM_TOTAL (SM_AB + NSTAGE * STAGE_BYTES)   // 100352  (2 CTAs/SM)

#define W_ELEMS ((size_t)NDIM * KDIM)

// Scratch (module globals -- allocation-free per harness rules)
__device__ __nv_bfloat16 g_xbf[(size_t)TOK * KDIM];
__device__ __nv_bfloat16 g_wbf[W_ELEMS];
__device__ float         g_ascale[TOK];
__device__ int           g_wmode;   // 0=int8 raw, 1=int32, 2=bf16, 3=f32

// ---------------------------------------------------------------------------
__device__ __forceinline__ uint32_t smem_u32(const void* p) {
    uint32_t a;
    asm("{ .reg .u64 t; cvta.to.shared.u64 t, %1; cvt.u32.u64 %0, t; }" : "=r"(a) : "l"(p));
    return a;
}

__device__ __forceinline__ void cp16(uint32_t dst, const void* src) {
    asm volatile("cp.async.cg.shared.global [%0], [%1], 16;" :: "r"(dst), "l"(src));
}

__device__ __forceinline__ void ldsm_x4(uint32_t* r, uint32_t addr) {
    asm volatile("ldmatrix.sync.aligned.m8n8.x4.shared.b16 {%0,%1,%2,%3}, [%4];"
                 : "=r"(r[0]), "=r"(r[1]), "=r"(r[2]), "=r"(r[3]) : "r"(addr));
}

__device__ __forceinline__ void mma_bf16_k16(float* c, const uint32_t* a, uint32_t b0, uint32_t b1) {
    asm volatile(
        "mma.sync.aligned.m16n8k16.row.col.f32.bf16.bf16.f32 "
        "{%0,%1,%2,%3}, {%4,%5,%6,%7}, {%8,%9}, {%0,%1,%2,%3};"
        : "+f"(c[0]), "+f"(c[1]), "+f"(c[2]), "+f"(c[3])
        : "r"(a[0]), "r"(a[1]), "r"(a[2]), "r"(a[3]), "r"(b0), "r"(b1));
}

// ---------------------------------------------------------------------------
// Weight format autodetect + direct-to-bf16 pack (proven rounds 4/7)
// ---------------------------------------------------------------------------
__global__ void detect_kernel(const void* w) {
    __shared__ int ok32, okf32, okbf;
    int tid = threadIdx.x;
    if (tid == 0) { ok32 = 1; okf32 = 1; okbf = 1; }
    __syncthreads();
    const int*            wi = (const int*)w;
    const float*          wf = (const float*)w;
    const __nv_bfloat16*  wb = (const __nv_bfloat16*)w;
#pragma unroll
    for (int i = 0; i < 4; i++) {
        int idx = tid * 4 + i;
        int v = wi[idx];
        if (v < -128 || v > 127) ok32 = 0;
        float f = wf[idx];
        if (!(f == rintf(f)) || f < -128.0f || f > 127.0f) okf32 = 0;
        float b = __bfloat162float(wb[idx]);
        if (!(b == rintf(b)) || b < -128.0f || b > 127.0f) okbf = 0;
    }
    __syncthreads();
    if (tid == 0)
        g_wmode = ok32 ? 1 : (okf32 ? 3 : (okbf ? 2 : 0));
}

__global__ void __launch_bounds__(256) pack_kernel(const void* w) {
    size_t g = (size_t)blockIdx.x * blockDim.x + threadIdx.x;
    if (g * 16 >= W_ELEMS) return;
    int mode = g_wmode;
    float f[16];
    if (mode == 0) {
        int8_t b[16];
        *(int4*)b = ((const int4*)w)[g];
#pragma unroll
        for (int j = 0; j < 16; j++) f[j] = (float)b[j];
    } else if (mode == 1) {
        const int4* wi = (const int4*)w + g * 4;
#pragma unroll
        for (int j = 0; j < 4; j++) {
            int4 v = wi[j];
            f[j * 4 + 0] = (float)(int8_t)v.x; f[j * 4 + 1] = (float)(int8_t)v.y;
            f[j * 4 + 2] = (float)(int8_t)v.z; f[j * 4 + 3] = (float)(int8_t)v.w;
        }
    } else if (mode == 2) {
        const __nv_bfloat16* wb = (const __nv_bfloat16*)w + g * 16;
#pragma unroll
        for (int j = 0; j < 16; j++) f[j] = __bfloat162float(wb[j]);
    } else {
        const float4* wf = (const float4*)w + g * 4;
#pragma unroll
        for (int j = 0; j < 4; j++) {
            float4 v = wf[j];
            f[j * 4 + 0] = v.x; f[j * 4 + 1] = v.y;
            f[j * 4 + 2] = v.z; f[j * 4 + 3] = v.w;
        }
    }
    uint32_t o[8];
#pragma unroll
    for (int j = 0; j < 8; j++) {
        __nv_bfloat162 h = __floats2bfloat162_rn(f[2 * j], f[2 * j + 1]);
        o[j] = *(uint32_t*)&h;
    }
    uint4* dst = (uint4*)(g_wbf + g * 16);
    dst[0] = make_uint4(o[0], o[1], o[2], o[3]);
    dst[1] = make_uint4(o[4], o[5], o[6], o[7]);
}

// ---------------------------------------------------------------------------
// Kernel 1: per-token dynamic quantization -> bf16 (int-valued)
// ---------------------------------------------------------------------------
__device__ __forceinline__ float q8f(float x, float s) {
    float r = rintf(__fdiv_rn(x, s));
    return fminf(fmaxf(r, -128.0f), 127.0f);
}

__global__ void __launch_bounds__(256) quant_kernel(const float* __restrict__ x) {
    int t = blockIdx.x;
    int tid = threadIdx.x;
    const float4* xr = (const float4*)(x + (size_t)t * KDIM);
    float4 v[4];
    float am = 0.0f;
#pragma unroll
    for (int i = 0; i < 4; i++) {
        v[i] = xr[tid * 4 + i];
        am = fmaxf(am, fmaxf(fmaxf(fabsf(v[i].x), fabsf(v[i].y)),
                             fmaxf(fabsf(v[i].z), fabsf(v[i].w))));
    }
    __shared__ float red[256];
    red[tid] = am;
    __syncthreads();
    for (int s = 128; s > 0; s >>= 1) {
        if (tid < s) red[tid] = fmaxf(red[tid], red[tid + s]);
        __syncthreads();
    }
    float s = fmaxf(__fdiv_rn(red[0], 127.0f), 1e-8f);
    if (tid == 0) g_ascale[t] = s;

    float q[16];
    q[0] = q8f(v[0].x, s);  q[1] = q8f(v[0].y, s);  q[2] = q8f(v[0].z, s);  q[3] = q8f(v[0].w, s);
    q[4] = q8f(v[1].x, s);  q[5] = q8f(v[1].y, s);  q[6] = q8f(v[1].z, s);  q[7] = q8f(v[1].w, s);
    q[8] = q8f(v[2].x, s);  q[9] = q8f(v[2].y, s);  q[10] = q8f(v[2].z, s); q[11] = q8f(v[2].w, s);
    q[12] = q8f(v[3].x, s); q[13] = q8f(v[3].y, s); q[14] = q8f(v[3].z, s); q[15] = q8f(v[3].w, s);

    uint32_t h[8];
#pragma unroll
    for (int j = 0; j < 8; j++) {
        __nv_bfloat162 hb = __floats2bfloat162_rn(q[2 * j], q[2 * j + 1]);
        h[j] = *(uint32_t*)&hb;
    }
    uint4* dst = (uint4*)(g_xbf + (size_t)t * KDIM + tid * 16);
    dst[0] = make_uint4(h[0], h[1], h[2], h[3]);
    dst[1] = make_uint4(h[4], h[5], h[6], h[7]);
}

// ---------------------------------------------------------------------------
// GEMM: bf16 HMMA, 128x128 tile, 256 thr (8 warps x 32x64), 3-stage,
// XOR-swizzled smem (conflict-free ldmatrix), 2 CTAs/SM
// ---------------------------------------------------------------------------
__device__ __forceinline__ void copy_chunk(const __nv_bfloat16* abase_g,
                                           const __nv_bfloat16* bbase_g,
                                           int c, int stage, uint32_t sb, int tid) {
    uint32_t st = sb + SM_AB + stage * STAGE_BYTES;
    // A: 128 rows x 128 B = 1024 cp16 -> 4 per thread
    const char* asrc = (const char*)abase_g + (size_t)c * KCB;
#pragma unroll
    for (int i = 0; i < 4; i++) {
        int idx = tid + i * 256;
        int row = idx >> 3, u = idx & 7;
        cp16(st + row * ROWB + ((u ^ (row & 7)) * 16),
             asrc + (size_t)row * (KDIM * 2) + u * 16);
    }
    // B: 128 rows x 128 B = 1024 cp16 -> 4 per thread
    const char* bsrc = (const char*)bbase_g + (size_t)c * KCB;
    uint32_t bb = st + A_BYTES;
#pragma unroll
    for (int i = 0; i < 4; i++) {
        int idx = tid + i * 256;
        int row = idx >> 3, u = idx & 7;
        cp16(bb + row * ROWB + ((u ^ (row & 7)) * 16),
             bsrc + (size_t)row * (KDIM * 2) + u * 16);
    }
}

__global__ void __launch_bounds__(256, 2) hmma_gemm(const float* __restrict__ wscale,
                                                    const float* __restrict__ bias,
                                                    float* __restrict__ out) {
    extern __shared__ char smem[];
    uint32_t sb = smem_u32(smem);
    int tid = threadIdx.x, wid = tid >> 5, lane = tid & 31;
    int m0 = blockIdx.y * TILE_M;
    int n0 = blockIdx.x * TILE_N;
    int wm = wid & 3;            // 4 M-strips of 32
    int wn = wid >> 2;           // 2 N-strips of 64

    float* smem_ws = (float*)(smem + SM_WS);
    float* smem_bs = (float*)(smem + SM_BS);
    if (tid < 128)      smem_ws[tid] = wscale[n0 + tid];
    else                smem_bs[tid - 128] = bias[n0 + tid - 128];

    int g = lane >> 3, lr = lane & 7;
    // Per-lane swizzled base: row*128 XOR (lr*16).  (row & 7 == lr for both
    // A and B tiles since tile row bases are multiples of 8.)
    // At use: addr = st + (off ^ kpart), kpart = logical 16B-unit offset
    // (compile-time), valid because off's bits [4:6] hold lr*16 and the XOR
    // permutes only those bits.
    uint32_t arow = (uint32_t)(wm * 32 + (g & 1) * 8 + lr);
    uint32_t aoff = arow * ROWB ^ ((arow & 7) * 16) ^ ((uint32_t)(g >> 1) * 16);
    uint32_t brow = (uint32_t)(wn * 64 + (g >> 1) * 8 + lr);
    uint32_t boff = (uint32_t)A_BYTES + (brow * ROWB ^ ((brow & 7) * 16) ^ ((uint32_t)(g & 1) * 16));

    float acc[2][8][4];
#pragma unroll
    for (int f = 0; f < 2; f++)
#pragma unroll
        for (int nf = 0; nf < 8; nf++)
#pragma unroll
            for (int i = 0; i < 4; i++) acc[f][nf][i] = 0.0f;

    const __nv_bfloat16* Ag = g_xbf + (size_t)m0 * KDIM;
    const __nv_bfloat16* Bg = g_wbf + (size_t)n0 * KDIM;

    copy_chunk(Ag, Bg, 0, 0, sb, tid);
    asm volatile("cp.async.commit_group;" ::: "memory");
    copy_chunk(Ag, Bg, 1, 1, sb, tid);
    asm volatile("cp.async.commit_group;" ::: "memory");

    for (int c = 0; c < NCH; c++) {
        if (c < NCH - 1) asm volatile("cp.async.wait_group 1;" ::: "memory");
        else             asm volatile("cp.async.wait_group 0;" ::: "memory");
        __syncthreads();
        if (c + 2 < NCH) {
            copy_chunk(Ag, Bg, c + 2, (c + 2) % NSTAGE, sb, tid);
            asm volatile("cp.async.commit_group;" ::: "memory");
        }

        uint32_t st = sb + SM_AB + (c % NSTAGE) * STAGE_BYTES;
#pragma unroll
        for (int ks = 0; ks < 4; ks++) {      // 4 x k16 (2 units of 16 B)
            uint32_t kpart = (uint32_t)(ks * 32);
            uint32_t a[2][4];
#pragma unroll
            for (int f = 0; f < 2; f++)
                ldsm_x4(a[f], st + f * (16 * ROWB) + (aoff ^ kpart));
            uint32_t b[4][4];
#pragma unroll
            for (int q = 0; q < 4; q++)
                ldsm_x4(b[q], st + q * (16 * ROWB) + (boff ^ kpart));
#pragma unroll
            for (int f = 0; f < 2; f++)
#pragma unroll
                for (int q = 0; q < 4; q++) {
                    mma_bf16_k16(acc[f][2 * q],     a[f], b[q][0], b[q][1]);
                    mma_bf16_k16(acc[f][2 * q + 1], a[f], b[q][2], b[q][3]);
                }
        }
    }

    int lrow = lane >> 2, lcol2 = (lane & 3) * 2;
#pragma unroll
    for (int f = 0; f < 2; f++) {
        int mA = m0 + wm * 32 + f * 16 + lrow;
        float as0 = g_ascale[mA];
        float as1 = g_ascale[mA + 8];
#pragma unroll
        for (int nf = 0; nf < 8; nf++) {
            int col = wn * 64 + nf * 8 + lcol2;
            float ws0 = smem_ws[col], ws1 = smem_ws[col + 1];
            float bs0 = smem_bs[col], bs1 = smem_bs[col + 1];
            float2 v0, v1;
            v0.x = fmaf(acc[f][nf][0] * as0, ws0, bs0);
            v0.y = fmaf(acc[f][nf][1] * as0, ws1, bs1);
            v1.x = fmaf(acc[f][nf][2] * as1, ws0, bs0);
            v1.y = fmaf(acc[f][nf][3] * as1, ws1, bs1);
            *(float2*)(out + (size_t)mA * NDIM + n0 + col) = v0;
            *(float2*)(out + (size_t)(mA + 8) * NDIM + n0 + col) = v1;
        }
    }
}

// ---------------------------------------------------------------------------
extern "C" void kernel_launch(void* const* d_in, const int* in_sizes, int n_in,
                              void* d_out, int out_size) {
    const float* x;
    const float* bs;
    if (in_sizes[0] == NDIM) {           // alphabetical: bias first
        bs = (const float*)d_in[0];
        x  = (const float*)d_in[3];
    } else {                             // dict order: x first
        x  = (const float*)d_in[0];
        bs = (const float*)d_in[3];
    }
    const void*  w  = d_in[1];
    const float* ws = (const float*)d_in[2];
    float* out = (float*)d_out;

    cudaFuncSetAttribute(hmma_gemm, cudaFuncAttributeMaxDynamicSharedMemorySize, SMEM_TOTAL);

    detect_kernel<<<1, 256>>>(w);
    pack_kernel<<<(int)((W_ELEMS / 16 + 255) / 256), 256>>>(w);
    quant_kernel<<<TOK, 256>>>(x);
    dim3 grid(NDIM / TILE_N, TOK / TILE_M);   // (96, 32)
    hmma_gemm<<<grid, 256, SMEM_TOTAL>>>(ws, bs, out);
}